// round 13
// baseline (speedup 1.0000x reference)
#include <cuda_runtime.h>
#include <cuda_fp16.h>
#include <cstdint>

// ---------------------------------------------------------------------------
// CategoricalGINEncoder on GB300 (sm_103a) — round 13
//  = round 10 exactly (best: 489.5us), except k_agg uses 2 warps per row
//    (each warp gathers a 256B half-row) to double latency-hiding parallelism.
// ---------------------------------------------------------------------------

#define NMAX 100000
#define EMAX 1600000
#define DIM  256

__device__ __half g_h0[(size_t)NMAX * DIM];
__device__ __half g_h1[(size_t)NMAX * DIM];
__device__ __half g_tabh[(size_t)4 * 1024 * DIM];
__device__ __align__(256) __half g_w1b[DIM * DIM];
__device__ __align__(256) __half g_w2a[DIM * DIM];
__device__ __align__(256) __half g_w2b[DIM * DIM];
__device__ int    g_deg[NMAX];
__device__ int    g_rowptr[NMAX + 1];
__device__ int    g_cursor[NMAX];
__device__ int    g_csr[EMAX];

// ------------------------------ half helpers -------------------------------

__device__ __forceinline__ void addh8(float* a, uint4 v) {
    float2 f;
    f = __half22float2(*(__half2*)&v.x); a[0] += f.x; a[1] += f.y;
    f = __half22float2(*(__half2*)&v.y); a[2] += f.x; a[3] += f.y;
    f = __half22float2(*(__half2*)&v.z); a[4] += f.x; a[5] += f.y;
    f = __half22float2(*(__half2*)&v.w); a[6] += f.x; a[7] += f.y;
}

__device__ __forceinline__ void addh4(float* a, uint2 v) {
    float2 f;
    f = __half22float2(*(__half2*)&v.x); a[0] += f.x; a[1] += f.y;
    f = __half22float2(*(__half2*)&v.y); a[2] += f.x; a[3] += f.y;
}

// ------------------------------ front kernel 1 ------------------------------

__global__ void k_front1(const int* __restrict__ ei, int* __restrict__ deg, int E,
                         const float* __restrict__ e0, const float* __restrict__ e1,
                         const float* __restrict__ e2, const float* __restrict__ e3,
                         const float* __restrict__ w1a, __half* __restrict__ T, int V,
                         const float* __restrict__ wf1, __half* __restrict__ wh1,
                         const float* __restrict__ wf2, __half* __restrict__ wh2,
                         const float* __restrict__ wf3, __half* __restrict__ wh3,
                         int nCnt, int nVb) {
    __shared__ float es[8 * 64];
    int b = blockIdx.x;
    int tid = threadIdx.x;
    if (b < nCnt) {
        int i = (b * 256 + tid) * 4;
        if (i >= E) return;
        if (i + 3 < E) {
            int4 d = *(const int4*)(ei + E + i);
            atomicAdd(&deg[d.x], 1);
            atomicAdd(&deg[d.y], 1);
            atomicAdd(&deg[d.z], 1);
            atomicAdd(&deg[d.w], 1);
        } else {
            for (; i < E; ++i) atomicAdd(&deg[ei[E + i]], 1);
        }
        return;
    }
    b -= nCnt;
    if (b < 4 * nVb) {
        int f = b / nVb;
        int v0 = (b % nVb) * 8;
        const float* emb = (f == 0) ? e0 : (f == 1) ? e1 : (f == 2) ? e2 : e3;
        #pragma unroll
        for (int i = 0; i < 2; ++i) {
            int idx = i * 256 + tid;
            int v = idx >> 6, k = idx & 63;
            es[idx] = (v0 + v < V) ? emb[(v0 + v) * 64 + k] : 0.f;
        }
        __syncthreads();
        float acc[8];
        #pragma unroll
        for (int v = 0; v < 8; ++v) acc[v] = 0.f;
        int c = tid;
        #pragma unroll 8
        for (int k = 0; k < 64; ++k) {
            float w = w1a[(f * 64 + k) * 256 + c];
            #pragma unroll
            for (int v = 0; v < 8; ++v) acc[v] = fmaf(es[v * 64 + k], w, acc[v]);
        }
        #pragma unroll
        for (int v = 0; v < 8; ++v)
            if (v0 + v < V)
                T[((size_t)f * 1024 + v0 + v) * 256 + c] = __float2half_rn(acc[v]);
        return;
    }
    b -= 4 * nVb;
    {
        int idx = b * 2048 + tid * 8;
        const float* src;
        __half* dst;
        int off;
        if (idx < DIM * DIM)            { src = wf1; dst = wh1; off = idx; }
        else if (idx < 2 * DIM * DIM)   { src = wf2; dst = wh2; off = idx - DIM * DIM; }
        else if (idx < 3 * DIM * DIM)   { src = wf3; dst = wh3; off = idx - 2 * DIM * DIM; }
        else return;
        float4 a = *(const float4*)(src + off);
        float4 bb = *(const float4*)(src + off + 4);
        __half2 h0 = __floats2half2_rn(a.x, a.y);
        __half2 h1 = __floats2half2_rn(a.z, a.w);
        __half2 h2 = __floats2half2_rn(bb.x, bb.y);
        __half2 h3 = __floats2half2_rn(bb.z, bb.w);
        uint4 o;
        o.x = *(uint32_t*)&h0; o.y = *(uint32_t*)&h1;
        o.z = *(uint32_t*)&h2; o.w = *(uint32_t*)&h3;
        *(uint4*)(dst + off) = o;
    }
}

// ------------------------------- scan (1 block) -----------------------------

__global__ void k_scan(const int* __restrict__ deg, int* __restrict__ rowptr,
                       int* __restrict__ cursor, int n) {
    __shared__ int sh[1024];
    int t = threadIdx.x;
    int chunk = (n + 1023) >> 10;
    int lo = t * chunk;
    int hi = min(lo + chunk, n);
    int s = 0;
    #pragma unroll 4
    for (int i = lo; i < hi; ++i) s += deg[i];
    sh[t] = s;
    __syncthreads();
    for (int off = 1; off < 1024; off <<= 1) {
        int v = (t >= off) ? sh[t - off] : 0;
        __syncthreads();
        sh[t] += v;
        __syncthreads();
    }
    int run = (t == 0) ? 0 : sh[t - 1];
    for (int i = lo; i < hi; ++i) {
        rowptr[i] = run;
        cursor[i] = run;
        run += deg[i];
    }
    if (lo < n && hi == n) rowptr[n] = run;
}

// ------------------------------ front kernel 2 ------------------------------

__global__ void k_front2(const int* __restrict__ ei, int* __restrict__ cursor,
                         int* __restrict__ csr, int E,
                         const int* __restrict__ xc, const __half* __restrict__ T,
                         __half* __restrict__ Z, int M, int nFill) {
    int b = blockIdx.x;
    int tid = threadIdx.x;
    if (b < nFill) {
        int i = (b * 256 + tid) * 4;
        if (i >= E) return;
        if (i + 3 < E) {
            int4 s = *(const int4*)(ei + i);
            int4 d = *(const int4*)(ei + E + i);
            csr[atomicAdd(&cursor[d.x], 1)] = s.x;
            csr[atomicAdd(&cursor[d.y], 1)] = s.y;
            csr[atomicAdd(&cursor[d.z], 1)] = s.z;
            csr[atomicAdd(&cursor[d.w], 1)] = s.w;
        } else {
            for (; i < E; ++i)
                csr[atomicAdd(&cursor[ei[E + i]], 1)] = ei[i];
        }
        return;
    }
    int idx = (b - nFill) * 256 + tid;
    if (idx >= M * 32) return;
    int node = idx >> 5;
    int q = idx & 31;
    int c0 = xc[node * 4 + 0];
    int c1 = xc[node * 4 + 1];
    int c2 = xc[node * 4 + 2];
    int c3 = xc[node * 4 + 3];
    float a[8] = {0.f, 0.f, 0.f, 0.f, 0.f, 0.f, 0.f, 0.f};
    addh8(a, *(const uint4*)(T + ((size_t)0 * 1024 + c0) * 256 + q * 8));
    addh8(a, *(const uint4*)(T + ((size_t)1 * 1024 + c1) * 256 + q * 8));
    addh8(a, *(const uint4*)(T + ((size_t)2 * 1024 + c2) * 256 + q * 8));
    addh8(a, *(const uint4*)(T + ((size_t)3 * 1024 + c3) * 256 + q * 8));
    __half2 h0 = __floats2half2_rn(a[0], a[1]);
    __half2 h1 = __floats2half2_rn(a[2], a[3]);
    __half2 h2 = __floats2half2_rn(a[4], a[5]);
    __half2 h3 = __floats2half2_rn(a[6], a[7]);
    uint4 o;
    o.x = *(uint32_t*)&h0; o.y = *(uint32_t*)&h1;
    o.z = *(uint32_t*)&h2; o.w = *(uint32_t*)&h3;
    ((uint4*)(Z + (size_t)node * 256))[q] = o;
}

// --------------------------- aggregation (half) ----------------------------
// TWO warps per row: warp handles a 256B half-row (uint2 per lane).

__global__ void k_agg(const __half* __restrict__ X, __half* __restrict__ Y,
                      const int* __restrict__ rowptr, const int* __restrict__ csr,
                      int M) {
    int gw = (blockIdx.x * blockDim.x + threadIdx.x) >> 5;
    int row = gw >> 1;
    int hf = gw & 1;
    int lane = threadIdx.x & 31;
    if (row >= M) return;
    int q = hf * 32 + lane;          // uint2 slot within the row (0..63)
    float a[4] = {0.f, 0.f, 0.f, 0.f};
    addh4(a, ((const uint2*)(X + (size_t)row * DIM))[q]);
    int e = rowptr[row], end = rowptr[row + 1];
    for (; e + 1 < end; e += 2) {
        int s0 = csr[e];
        int s1 = csr[e + 1];
        uint2 u = ((const uint2*)(X + (size_t)s0 * DIM))[q];
        uint2 v = ((const uint2*)(X + (size_t)s1 * DIM))[q];
        addh4(a, u);
        addh4(a, v);
    }
    if (e < end) {
        int s = csr[e];
        addh4(a, ((const uint2*)(X + (size_t)s * DIM))[q]);
    }
    __half2 h0 = __floats2half2_rn(a[0], a[1]);
    __half2 h1 = __floats2half2_rn(a[2], a[3]);
    uint2 o;
    o.x = *(uint32_t*)&h0;
    o.y = *(uint32_t*)&h1;
    ((uint2*)(Y + (size_t)row * DIM))[q] = o;
}

// ------------------------------ fused conv ---------------------------------
// (round-10 form: 3-slot cp.async ring, depth 2)

#define XPH  264
#define XS_H (64 * XPH)
#define WPH  264
#define W_CH (32 * WPH)
#define CONV_SMEM_BYTES ((XS_H + 3 * W_CH) * 2 + 64 * 4 * 8)   // 86528 B

__device__ __forceinline__ void ldsm4(uint32_t* r, uint32_t addr) {
    asm volatile("ldmatrix.sync.aligned.m8n8.x4.shared.b16 {%0,%1,%2,%3},[%4];"
                 : "=r"(r[0]), "=r"(r[1]), "=r"(r[2]), "=r"(r[3]) : "r"(addr));
}
__device__ __forceinline__ void ldsm4t(uint32_t* r, uint32_t addr) {
    asm volatile("ldmatrix.sync.aligned.m8n8.x4.trans.shared.b16 {%0,%1,%2,%3},[%4];"
                 : "=r"(r[0]), "=r"(r[1]), "=r"(r[2]), "=r"(r[3]) : "r"(addr));
}
__device__ __forceinline__ void mma16(float* c, const uint32_t* a,
                                      uint32_t b0, uint32_t b1) {
    asm volatile(
        "mma.sync.aligned.m16n8k16.row.col.f32.f16.f16.f32 "
        "{%0,%1,%2,%3},{%4,%5,%6,%7},{%8,%9},{%0,%1,%2,%3};\n"
        : "+f"(c[0]), "+f"(c[1]), "+f"(c[2]), "+f"(c[3])
        : "r"(a[0]), "r"(a[1]), "r"(a[2]), "r"(a[3]), "r"(b0), "r"(b1));
}
__device__ __forceinline__ void cp16(uint32_t dst, const void* src) {
    asm volatile("cp.async.cg.shared.global [%0], [%1], 16;\n"
                 :: "r"(dst), "l"(src));
}

__device__ __forceinline__ void gemm_h(
    const __half* __restrict__ W,
    uint32_t xs_b, uint32_t ws_b,
    float (&c)[2][8][4], int tid, int wm, int wn, int lane) {
    const int krow = tid >> 5;
    const int n8 = tid & 31;
    const int aro = ((lane >> 3) & 1) * 8 + (lane & 7);
    const int kco = (lane >> 4) * 8;

#define ISSUE_W(ck, s) do {                                                   \
        const __half* _src = W + (size_t)(ck) * 32 * 256;                     \
        uint32_t _dst = ws_b + 2u * (uint32_t)((s) * W_CH);                   \
        _Pragma("unroll")                                                     \
        for (int _i = 0; _i < 4; ++_i) {                                      \
            int _row = krow + _i * 8;                                         \
            cp16(_dst + 2u * (uint32_t)(_row * WPH + n8 * 8),                 \
                 _src + (size_t)_row * 256 + n8 * 8);                         \
        }                                                                     \
        asm volatile("cp.async.commit_group;");                               \
    } while (0)

    ISSUE_W(0, 0);
    ISSUE_W(1, 1);

    #pragma unroll 1
    for (int it = 0; it < 8; ++it) {
        if (it < 7) asm volatile("cp.async.wait_group 1;");
        else        asm volatile("cp.async.wait_group 0;");
        __syncthreads();
        if (it < 6) {
            int s = (it + 2) % 3;
            ISSUE_W(it + 2, s);
        }
        uint32_t wsb = ws_b + 2u * (uint32_t)((it % 3) * W_CH);
        #pragma unroll
        for (int kt = 0; kt < 2; ++kt) {
            const int ktb = it * 32 + kt * 16;
            const int ktL = kt * 16;
            uint32_t a[2][4];
            #pragma unroll
            for (int mt = 0; mt < 2; ++mt)
                ldsm4(a[mt], xs_b +
                      2u * ((wm * 32 + mt * 16 + aro) * XPH + ktb + kco));
            #pragma unroll
            for (int hf = 0; hf < 2; ++hf) {
                uint32_t b[2][4];
                #pragma unroll
                for (int p = 0; p < 2; ++p) {
                    int np = hf * 2 + p;
                    ldsm4t(b[p], wsb +
                           2u * ((ktL + aro) * WPH + wn * 64 + np * 16 + kco));
                }
                #pragma unroll
                for (int mt = 0; mt < 2; ++mt)
                    #pragma unroll
                    for (int q = 0; q < 4; ++q)
                        mma16(c[mt][hf * 4 + q], a[mt],
                              b[q >> 1][(q & 1) * 2], b[q >> 1][(q & 1) * 2 + 1]);
            }
        }
    }
#undef ISSUE_W
}

__global__ void __launch_bounds__(256, 2) k_conv(
    const __half* __restrict__ A,  const float* __restrict__ bIn,
    const __half* __restrict__ W1, const float* __restrict__ b1,
    const float* __restrict__ lng, const float* __restrict__ lnb,
    const __half* __restrict__ W2,
    __half* __restrict__ OutH, float* __restrict__ OutF,
    int M, int reluLN, int hasG2) {
    extern __shared__ __half smh[];
    __half* XS = smh;
    float2* part = (float2*)(smh + XS_H + 3 * W_CH);

    const int tid  = threadIdx.x;
    const int warp = tid >> 5, lane = tid & 31;
    const int wm = warp >> 2;
    const int wn = warp & 3;
    const int g  = lane >> 2;
    const int tq = lane & 3;
    const long blockRow = (long)blockIdx.x * 64;
    uint32_t xs_b = (uint32_t)__cvta_generic_to_shared(XS);
    uint32_t ws_b = (uint32_t)__cvta_generic_to_shared(smh + XS_H);

    #pragma unroll
    for (int i = 0; i < 8; ++i) {
        int id = i * 256 + tid;
        int row = id >> 5;
        int q = id & 31;
        long r = blockRow + row;
        if (r > M - 1) r = M - 1;
        uint4 v = ((const uint4*)(A + r * 256))[q];
        float4 ba = *(const float4*)(bIn + q * 8);
        float4 bb = *(const float4*)(bIn + q * 8 + 4);
        float f[8];
        float2 t;
        t = __half22float2(*(__half2*)&v.x); f[0] = t.x; f[1] = t.y;
        t = __half22float2(*(__half2*)&v.y); f[2] = t.x; f[3] = t.y;
        t = __half22float2(*(__half2*)&v.z); f[4] = t.x; f[5] = t.y;
        t = __half22float2(*(__half2*)&v.w); f[6] = t.x; f[7] = t.y;
        f[0] = fmaxf(f[0] + ba.x, 0.f); f[1] = fmaxf(f[1] + ba.y, 0.f);
        f[2] = fmaxf(f[2] + ba.z, 0.f); f[3] = fmaxf(f[3] + ba.w, 0.f);
        f[4] = fmaxf(f[4] + bb.x, 0.f); f[5] = fmaxf(f[5] + bb.y, 0.f);
        f[6] = fmaxf(f[6] + bb.z, 0.f); f[7] = fmaxf(f[7] + bb.w, 0.f);
        __half2 h0 = __floats2half2_rn(f[0], f[1]);
        __half2 h1 = __floats2half2_rn(f[2], f[3]);
        __half2 h2 = __floats2half2_rn(f[4], f[5]);
        __half2 h3 = __floats2half2_rn(f[6], f[7]);
        uint4 o;
        o.x = *(uint32_t*)&h0; o.y = *(uint32_t*)&h1;
        o.z = *(uint32_t*)&h2; o.w = *(uint32_t*)&h3;
        *(uint4*)(XS + row * XPH + q * 8) = o;
    }

    float c[2][8][4];
    #pragma unroll
    for (int i = 0; i < 2; ++i)
        #pragma unroll
        for (int j = 0; j < 8; ++j)
            #pragma unroll
            for (int k = 0; k < 4; ++k) c[i][j][k] = 0.f;

    gemm_h(W1, xs_b, ws_b, c, tid, wm, wn, lane);

    #pragma unroll
    for (int mt = 0; mt < 2; ++mt)
        #pragma unroll
        for (int nt = 0; nt < 8; ++nt) {
            int col = wn * 64 + nt * 8 + tq * 2;
            float2 bv = *(const float2*)(b1 + col);
            c[mt][nt][0] += bv.x; c[mt][nt][1] += bv.y;
            c[mt][nt][2] += bv.x; c[mt][nt][3] += bv.y;
            if (reluLN) {
                c[mt][nt][0] = fmaxf(c[mt][nt][0], 0.f);
                c[mt][nt][1] = fmaxf(c[mt][nt][1], 0.f);
                c[mt][nt][2] = fmaxf(c[mt][nt][2], 0.f);
                c[mt][nt][3] = fmaxf(c[mt][nt][3], 0.f);
            }
        }

    float s[2][2], ss[2][2];
    #pragma unroll
    for (int mt = 0; mt < 2; ++mt)
        #pragma unroll
        for (int hf = 0; hf < 2; ++hf) {
            float a = 0.f, b = 0.f;
            #pragma unroll
            for (int nt = 0; nt < 8; ++nt) {
                float v0 = c[mt][nt][hf * 2];
                float v1 = c[mt][nt][hf * 2 + 1];
                a += v0 + v1;
                b += v0 * v0 + v1 * v1;
            }
            #pragma unroll
            for (int o = 1; o <= 2; o <<= 1) {
                a += __shfl_xor_sync(0xffffffffu, a, o);
                b += __shfl_xor_sync(0xffffffffu, b, o);
            }
            s[mt][hf] = a;
            ss[mt][hf] = b;
        }
    if (tq == 0) {
        #pragma unroll
        for (int mt = 0; mt < 2; ++mt)
            #pragma unroll
            for (int hf = 0; hf < 2; ++hf) {
                int row = wm * 32 + mt * 16 + hf * 8 + g;
                part[row * 4 + wn] = make_float2(s[mt][hf], ss[mt][hf]);
            }
    }
    __syncthreads();

    #pragma unroll
    for (int mt = 0; mt < 2; ++mt)
        #pragma unroll
        for (int hf = 0; hf < 2; ++hf) {
            int row = wm * 32 + mt * 16 + hf * 8 + g;
            float2 p0 = part[row * 4 + 0];
            float2 p1 = part[row * 4 + 1];
            float2 p2 = part[row * 4 + 2];
            float2 p3 = part[row * 4 + 3];
            float sum = p0.x + p1.x + p2.x + p3.x;
            float sq  = p0.y + p1.y + p2.y + p3.y;
            float mean = sum * (1.f / 256.f);
            float var  = sq * (1.f / 256.f) - mean * mean;
            float rstd = rsqrtf(var + 1e-5f);
            long grow = blockRow + row;
            #pragma unroll
            for (int nt = 0; nt < 8; ++nt) {
                int col = wn * 64 + nt * 8 + tq * 2;
                float2 gv = *(const float2*)(lng + col);
                float2 bv = *(const float2*)(lnb + col);
                float o0 = (c[mt][nt][hf * 2]     - mean) * rstd * gv.x + bv.x;
                float o1 = (c[mt][nt][hf * 2 + 1] - mean) * rstd * gv.y + bv.y;
                if (hasG2) {
                    __half2 h = __floats2half2_rn(o0, o1);
                    *(uint32_t*)(XS + row * XPH + col) = *(uint32_t*)&h;
                } else if (grow < M) {
                    float2 t = {o0, o1};
                    *(float2*)(OutF + grow * 256 + col) = t;
                }
            }
        }
    if (!hasG2) return;
    __syncthreads();

    #pragma unroll
    for (int i = 0; i < 2; ++i)
        #pragma unroll
        for (int j = 0; j < 8; ++j)
            #pragma unroll
            for (int k = 0; k < 4; ++k) c[i][j][k] = 0.f;

    gemm_h(W2, xs_b, ws_b, c, tid, wm, wn, lane);

    #pragma unroll
    for (int mt = 0; mt < 2; ++mt) {
        long rb = blockRow + wm * 32 + mt * 16;
        long r0 = rb + g;
        long r1 = rb + 8 + g;
        #pragma unroll
        for (int nt = 0; nt < 8; ++nt) {
            int col = wn * 64 + nt * 8 + tq * 2;
            if (r0 < M) {
                __half2 h = __floats2half2_rn(c[mt][nt][0], c[mt][nt][1]);
                *(uint32_t*)(OutH + r0 * 256 + col) = *(uint32_t*)&h;
            }
            if (r1 < M) {
                __half2 h = __floats2half2_rn(c[mt][nt][2], c[mt][nt][3]);
                *(uint32_t*)(OutH + r1 * 256 + col) = *(uint32_t*)&h;
            }
        }
    }
}

// --------------------------------- driver ---------------------------------

extern "C" void kernel_launch(void* const* d_in, const int* in_sizes, int n_in,
                              void* d_out, int out_size) {
    const int*   xcat = (const int*)d_in[0];
    const int*   ei   = (const int*)d_in[1];
    const float* e0   = (const float*)d_in[2];
    const float* e1   = (const float*)d_in[3];
    const float* e2   = (const float*)d_in[4];
    const float* e3   = (const float*)d_in[5];
    const float* w1a  = (const float*)d_in[6];
    const float* b1a  = (const float*)d_in[7];
    const float* w1b  = (const float*)d_in[8];
    const float* b1b  = (const float*)d_in[9];
    const float* w2a  = (const float*)d_in[10];
    const float* b2a  = (const float*)d_in[11];
    const float* w2b  = (const float*)d_in[12];
    const float* b2b  = (const float*)d_in[13];
    const float* ln1g = (const float*)d_in[14];
    const float* ln1b = (const float*)d_in[15];
    const float* ln2g = (const float*)d_in[16];
    const float* ln2b = (const float*)d_in[17];

    int M = in_sizes[0] / 4;
    int E = in_sizes[1] / 2;
    int V = in_sizes[2] / 64;

    __half *h0, *h1, *tabh, *hw1b, *hw2a, *hw2b;
    int *deg, *rowptr, *cursor, *csr;
    cudaGetSymbolAddress((void**)&h0, g_h0);
    cudaGetSymbolAddress((void**)&h1, g_h1);
    cudaGetSymbolAddress((void**)&tabh, g_tabh);
    cudaGetSymbolAddress((void**)&hw1b, g_w1b);
    cudaGetSymbolAddress((void**)&hw2a, g_w2a);
    cudaGetSymbolAddress((void**)&hw2b, g_w2b);
    cudaGetSymbolAddress((void**)&deg, g_deg);
    cudaGetSymbolAddress((void**)&rowptr, g_rowptr);
    cudaGetSymbolAddress((void**)&cursor, g_cursor);
    cudaGetSymbolAddress((void**)&csr, g_csr);

    cudaFuncSetAttribute(k_conv, cudaFuncAttributeMaxDynamicSharedMemorySize,
                         CONV_SMEM_BYTES);

    int aggGrid = (M * 2 + 7) / 8;     // 2 warps per row, 8 warps/block
    int convGrid = (M + 63) / 64;

    int nCnt = (E / 4 + 255) / 256;
    int nVb = (V + 7) / 8;
    int nCvt = (3 * DIM * DIM + 2047) / 2048;
    int nFill = nCnt;
    int nZ0 = (M * 32 + 255) / 256;

    cudaMemsetAsync(deg, 0, (size_t)M * sizeof(int), 0);
    k_front1<<<nCnt + 4 * nVb + nCvt, 256>>>(ei, deg, E,
                                             e0, e1, e2, e3, w1a, tabh, V,
                                             w1b, hw1b, w2a, hw2a, w2b, hw2b,
                                             nCnt, nVb);
    k_scan<<<1, 1024>>>(deg, rowptr, cursor, M);
    k_front2<<<nFill + nZ0, 256>>>(ei, cursor, csr, E,
                                   xcat, tabh, h0, M, nFill);

    // conv1: a1 = agg(z0); h = LN1(relu(relu(a1+b1a)@W1b+b1b)); u = h@W2a
    k_agg<<<aggGrid, 256>>>(h0, h1, rowptr, csr, M);
    k_conv<<<convGrid, 256, CONV_SMEM_BYTES>>>(h1, b1a, hw1b, b1b, ln1g, ln1b,
                                               hw2a, h0, nullptr, M, 1, 1);

    // conv2: a2 = agg(u); out = LN2(relu(a2+b2a)@W2b+b2b)
    k_agg<<<aggGrid, 256>>>(h0, h1, rowptr, csr, M);
    k_conv<<<convGrid, 256, CONV_SMEM_BYTES>>>(h1, b2a, hw2b, b2b, ln2g, ln2b,
                                               nullptr, nullptr, (float*)d_out,
                                               M, 0, 0);
}

// round 14
// speedup vs baseline: 1.0541x; 1.0541x over previous
#include <cuda_runtime.h>
#include <cuda_fp16.h>
#include <cstdint>

// ---------------------------------------------------------------------------
// CategoricalGINEncoder on GB300 (sm_103a) — round 14
//  = round 10 exactly (best: 489.5us; agg at L1tex request floor, conv at
//    mma.sync floor, fused front kernels)
//  + Programmatic Dependent Launch on the whole chain:
//     successors launch into predecessor tails; k_conv primes its W cp.async
//     pipeline BEFORE griddepcontrol.wait (W written 3+ kernels back).
// ---------------------------------------------------------------------------

#define NMAX 100000
#define EMAX 1600000
#define DIM  256

__device__ __half g_h0[(size_t)NMAX * DIM];
__device__ __half g_h1[(size_t)NMAX * DIM];
__device__ __half g_tabh[(size_t)4 * 1024 * DIM];
__device__ __align__(256) __half g_w1b[DIM * DIM];
__device__ __align__(256) __half g_w2a[DIM * DIM];
__device__ __align__(256) __half g_w2b[DIM * DIM];
__device__ int    g_deg[NMAX];
__device__ int    g_rowptr[NMAX + 1];
__device__ int    g_cursor[NMAX];
__device__ int    g_csr[EMAX];

__device__ __forceinline__ void pdl_wait() {
    asm volatile("griddepcontrol.wait;" ::: "memory");
}
__device__ __forceinline__ void pdl_launch_dep() {
    asm volatile("griddepcontrol.launch_dependents;");
}

// ------------------------------ half helpers -------------------------------

__device__ __forceinline__ void addh8(float* a, uint4 v) {
    float2 f;
    f = __half22float2(*(__half2*)&v.x); a[0] += f.x; a[1] += f.y;
    f = __half22float2(*(__half2*)&v.y); a[2] += f.x; a[3] += f.y;
    f = __half22float2(*(__half2*)&v.z); a[4] += f.x; a[5] += f.y;
    f = __half22float2(*(__half2*)&v.w); a[6] += f.x; a[7] += f.y;
}

// ------------------------------ front kernel 1 ------------------------------

__global__ void k_front1(const int* __restrict__ ei, int* __restrict__ deg, int E,
                         const float* __restrict__ e0, const float* __restrict__ e1,
                         const float* __restrict__ e2, const float* __restrict__ e3,
                         const float* __restrict__ w1a, __half* __restrict__ T, int V,
                         const float* __restrict__ wf1, __half* __restrict__ wh1,
                         const float* __restrict__ wf2, __half* __restrict__ wh2,
                         const float* __restrict__ wf3, __half* __restrict__ wh3,
                         int nCnt, int nVb) {
    __shared__ float es[8 * 64];
    int b = blockIdx.x;
    int tid = threadIdx.x;
    if (b < nCnt) {
        pdl_wait();                      // deg memset must be done
        int i = (b * 256 + tid) * 4;
        if (i < E) {
            if (i + 3 < E) {
                int4 d = *(const int4*)(ei + E + i);
                atomicAdd(&deg[d.x], 1);
                atomicAdd(&deg[d.y], 1);
                atomicAdd(&deg[d.z], 1);
                atomicAdd(&deg[d.w], 1);
            } else {
                for (; i < E; ++i) atomicAdd(&deg[ei[E + i]], 1);
            }
        }
        pdl_launch_dep();
        return;
    }
    b -= nCnt;
    if (b < 4 * nVb) {
        int f = b / nVb;
        int v0 = (b % nVb) * 8;
        const float* emb = (f == 0) ? e0 : (f == 1) ? e1 : (f == 2) ? e2 : e3;
        #pragma unroll
        for (int i = 0; i < 2; ++i) {
            int idx = i * 256 + tid;
            int v = idx >> 6, k = idx & 63;
            es[idx] = (v0 + v < V) ? emb[(v0 + v) * 64 + k] : 0.f;
        }
        __syncthreads();
        float acc[8];
        #pragma unroll
        for (int v = 0; v < 8; ++v) acc[v] = 0.f;
        int c = tid;
        #pragma unroll 8
        for (int k = 0; k < 64; ++k) {
            float w = w1a[(f * 64 + k) * 256 + c];
            #pragma unroll
            for (int v = 0; v < 8; ++v) acc[v] = fmaf(es[v * 64 + k], w, acc[v]);
        }
        #pragma unroll
        for (int v = 0; v < 8; ++v)
            if (v0 + v < V)
                T[((size_t)f * 1024 + v0 + v) * 256 + c] = __float2half_rn(acc[v]);
        pdl_launch_dep();
        return;
    }
    b -= 4 * nVb;
    {
        int idx = b * 2048 + tid * 8;
        const float* src;
        __half* dst;
        int off;
        if (idx < DIM * DIM)            { src = wf1; dst = wh1; off = idx; }
        else if (idx < 2 * DIM * DIM)   { src = wf2; dst = wh2; off = idx - DIM * DIM; }
        else if (idx < 3 * DIM * DIM)   { src = wf3; dst = wh3; off = idx - 2 * DIM * DIM; }
        else { pdl_launch_dep(); return; }
        float4 a = *(const float4*)(src + off);
        float4 bb = *(const float4*)(src + off + 4);
        __half2 h0 = __floats2half2_rn(a.x, a.y);
        __half2 h1 = __floats2half2_rn(a.z, a.w);
        __half2 h2 = __floats2half2_rn(bb.x, bb.y);
        __half2 h3 = __floats2half2_rn(bb.z, bb.w);
        uint4 o;
        o.x = *(uint32_t*)&h0; o.y = *(uint32_t*)&h1;
        o.z = *(uint32_t*)&h2; o.w = *(uint32_t*)&h3;
        *(uint4*)(dst + off) = o;
        pdl_launch_dep();
    }
}

// ------------------------------- scan (1 block) -----------------------------

__global__ void k_scan(const int* __restrict__ deg, int* __restrict__ rowptr,
                       int* __restrict__ cursor, int n) {
    __shared__ int sh[1024];
    int t = threadIdx.x;
    int chunk = (n + 1023) >> 10;
    int lo = t * chunk;
    int hi = min(lo + chunk, n);
    pdl_wait();
    int s = 0;
    #pragma unroll 4
    for (int i = lo; i < hi; ++i) s += deg[i];
    sh[t] = s;
    __syncthreads();
    for (int off = 1; off < 1024; off <<= 1) {
        int v = (t >= off) ? sh[t - off] : 0;
        __syncthreads();
        sh[t] += v;
        __syncthreads();
    }
    int run = (t == 0) ? 0 : sh[t - 1];
    for (int i = lo; i < hi; ++i) {
        rowptr[i] = run;
        cursor[i] = run;
        run += deg[i];
    }
    if (lo < n && hi == n) rowptr[n] = run;
    pdl_launch_dep();
}

// ------------------------------ front kernel 2 ------------------------------

__global__ void k_front2(const int* __restrict__ ei, int* __restrict__ cursor,
                         int* __restrict__ csr, int E,
                         const int* __restrict__ xc, const __half* __restrict__ T,
                         __half* __restrict__ Z, int M, int nFill) {
    int b = blockIdx.x;
    int tid = threadIdx.x;
    if (b < nFill) {
        pdl_wait();                      // cursor from scan
        int i = (b * 256 + tid) * 4;
        if (i < E) {
            if (i + 3 < E) {
                int4 s = *(const int4*)(ei + i);
                int4 d = *(const int4*)(ei + E + i);
                csr[atomicAdd(&cursor[d.x], 1)] = s.x;
                csr[atomicAdd(&cursor[d.y], 1)] = s.y;
                csr[atomicAdd(&cursor[d.z], 1)] = s.z;
                csr[atomicAdd(&cursor[d.w], 1)] = s.w;
            } else {
                for (; i < E; ++i)
                    csr[atomicAdd(&cursor[ei[E + i]], 1)] = ei[i];
            }
        }
        pdl_launch_dep();
        return;
    }
    int idx = (b - nFill) * 256 + tid;
    if (idx >= M * 32) { pdl_launch_dep(); return; }
    int node = idx >> 5;
    int q = idx & 31;
    // T written by front1 (2 kernels back): safe before wait by transitivity.
    int c0 = xc[node * 4 + 0];
    int c1 = xc[node * 4 + 1];
    int c2 = xc[node * 4 + 2];
    int c3 = xc[node * 4 + 3];
    float a[8] = {0.f, 0.f, 0.f, 0.f, 0.f, 0.f, 0.f, 0.f};
    addh8(a, *(const uint4*)(T + ((size_t)0 * 1024 + c0) * 256 + q * 8));
    addh8(a, *(const uint4*)(T + ((size_t)1 * 1024 + c1) * 256 + q * 8));
    addh8(a, *(const uint4*)(T + ((size_t)2 * 1024 + c2) * 256 + q * 8));
    addh8(a, *(const uint4*)(T + ((size_t)3 * 1024 + c3) * 256 + q * 8));
    __half2 h0 = __floats2half2_rn(a[0], a[1]);
    __half2 h1 = __floats2half2_rn(a[2], a[3]);
    __half2 h2 = __floats2half2_rn(a[4], a[5]);
    __half2 h3 = __floats2half2_rn(a[6], a[7]);
    uint4 o;
    o.x = *(uint32_t*)&h0; o.y = *(uint32_t*)&h1;
    o.z = *(uint32_t*)&h2; o.w = *(uint32_t*)&h3;
    ((uint4*)(Z + (size_t)node * 256))[q] = o;
    pdl_launch_dep();
}

// --------------------------- aggregation (half) ----------------------------
// warp per row, unroll-2, uint4/lane (proven optimum)

__global__ void k_agg(const __half* __restrict__ X, __half* __restrict__ Y,
                      const int* __restrict__ rowptr, const int* __restrict__ csr,
                      int M) {
    int w = (blockIdx.x * blockDim.x + threadIdx.x) >> 5;
    int lane = threadIdx.x & 31;
    pdl_wait();                          // X / csr from predecessors
    if (w >= M) { pdl_launch_dep(); return; }
    float a[8] = {0.f, 0.f, 0.f, 0.f, 0.f, 0.f, 0.f, 0.f};
    addh8(a, ((const uint4*)(X + (size_t)w * DIM))[lane]);
    int e = rowptr[w], end = rowptr[w + 1];
    for (; e + 1 < end; e += 2) {
        int s0 = csr[e];
        int s1 = csr[e + 1];
        uint4 u = ((const uint4*)(X + (size_t)s0 * DIM))[lane];
        uint4 v = ((const uint4*)(X + (size_t)s1 * DIM))[lane];
        addh8(a, u);
        addh8(a, v);
    }
    if (e < end) {
        int s = csr[e];
        addh8(a, ((const uint4*)(X + (size_t)s * DIM))[lane]);
    }
    __half2 h0 = __floats2half2_rn(a[0], a[1]);
    __half2 h1 = __floats2half2_rn(a[2], a[3]);
    __half2 h2 = __floats2half2_rn(a[4], a[5]);
    __half2 h3 = __floats2half2_rn(a[6], a[7]);
    uint4 o;
    o.x = *(uint32_t*)&h0; o.y = *(uint32_t*)&h1;
    o.z = *(uint32_t*)&h2; o.w = *(uint32_t*)&h3;
    ((uint4*)(Y + (size_t)w * DIM))[lane] = o;
    pdl_launch_dep();
}

// ------------------------------ fused conv ---------------------------------

#define XPH  264
#define XS_H (64 * XPH)
#define WPH  264
#define W_CH (32 * WPH)
#define CONV_SMEM_BYTES ((XS_H + 3 * W_CH) * 2 + 64 * 4 * 8)   // 86528 B

__device__ __forceinline__ void ldsm4(uint32_t* r, uint32_t addr) {
    asm volatile("ldmatrix.sync.aligned.m8n8.x4.shared.b16 {%0,%1,%2,%3},[%4];"
                 : "=r"(r[0]), "=r"(r[1]), "=r"(r[2]), "=r"(r[3]) : "r"(addr));
}
__device__ __forceinline__ void ldsm4t(uint32_t* r, uint32_t addr) {
    asm volatile("ldmatrix.sync.aligned.m8n8.x4.trans.shared.b16 {%0,%1,%2,%3},[%4];"
                 : "=r"(r[0]), "=r"(r[1]), "=r"(r[2]), "=r"(r[3]) : "r"(addr));
}
__device__ __forceinline__ void mma16(float* c, const uint32_t* a,
                                      uint32_t b0, uint32_t b1) {
    asm volatile(
        "mma.sync.aligned.m16n8k16.row.col.f32.f16.f16.f32 "
        "{%0,%1,%2,%3},{%4,%5,%6,%7},{%8,%9},{%0,%1,%2,%3};\n"
        : "+f"(c[0]), "+f"(c[1]), "+f"(c[2]), "+f"(c[3])
        : "r"(a[0]), "r"(a[1]), "r"(a[2]), "r"(a[3]), "r"(b0), "r"(b1));
}
__device__ __forceinline__ void cp16(uint32_t dst, const void* src) {
    asm volatile("cp.async.cg.shared.global [%0], [%1], 16;\n"
                 :: "r"(dst), "l"(src));
}

__device__ __forceinline__ void issue_w(const __half* __restrict__ W, int ck,
                                        int slot, uint32_t ws_b,
                                        int krow, int n8) {
    const __half* src = W + (size_t)ck * 32 * 256;
    uint32_t dst = ws_b + 2u * (uint32_t)(slot * W_CH);
    #pragma unroll
    for (int i = 0; i < 4; ++i) {
        int row = krow + i * 8;
        cp16(dst + 2u * (uint32_t)(row * WPH + n8 * 8),
             src + (size_t)row * 256 + n8 * 8);
    }
    asm volatile("cp.async.commit_group;");
}

// 3-slot ring, depth 2 (round-10 form). If primed, chunks 0,1 already issued.
__device__ __forceinline__ void gemm_h(
    const __half* __restrict__ W, bool primed,
    uint32_t xs_b, uint32_t ws_b,
    float (&c)[2][8][4], int tid, int wm, int wn, int lane) {
    const int krow = tid >> 5;
    const int n8 = tid & 31;
    const int aro = ((lane >> 3) & 1) * 8 + (lane & 7);
    const int kco = (lane >> 4) * 8;

    if (!primed) {
        issue_w(W, 0, 0, ws_b, krow, n8);
        issue_w(W, 1, 1, ws_b, krow, n8);
    }

    #pragma unroll 1
    for (int it = 0; it < 8; ++it) {
        if (it < 7) asm volatile("cp.async.wait_group 1;");
        else        asm volatile("cp.async.wait_group 0;");
        __syncthreads();
        if (it < 6)
            issue_w(W, it + 2, (it + 2) % 3, ws_b, krow, n8);
        uint32_t wsb = ws_b + 2u * (uint32_t)((it % 3) * W_CH);
        #pragma unroll
        for (int kt = 0; kt < 2; ++kt) {
            const int ktb = it * 32 + kt * 16;
            const int ktL = kt * 16;
            uint32_t a[2][4];
            #pragma unroll
            for (int mt = 0; mt < 2; ++mt)
                ldsm4(a[mt], xs_b +
                      2u * ((wm * 32 + mt * 16 + aro) * XPH + ktb + kco));
            #pragma unroll
            for (int hf = 0; hf < 2; ++hf) {
                uint32_t b[2][4];
                #pragma unroll
                for (int p = 0; p < 2; ++p) {
                    int np = hf * 2 + p;
                    ldsm4t(b[p], wsb +
                           2u * ((ktL + aro) * WPH + wn * 64 + np * 16 + kco));
                }
                #pragma unroll
                for (int mt = 0; mt < 2; ++mt)
                    #pragma unroll
                    for (int q = 0; q < 4; ++q)
                        mma16(c[mt][hf * 4 + q], a[mt],
                              b[q >> 1][(q & 1) * 2], b[q >> 1][(q & 1) * 2 + 1]);
            }
        }
    }
}

__global__ void __launch_bounds__(256, 2) k_conv(
    const __half* __restrict__ A,  const float* __restrict__ bIn,
    const __half* __restrict__ W1, const float* __restrict__ b1,
    const float* __restrict__ lng, const float* __restrict__ lnb,
    const __half* __restrict__ W2,
    __half* __restrict__ OutH, float* __restrict__ OutF,
    int M, int reluLN, int hasG2) {
    extern __shared__ __half smh[];
    __half* XS = smh;
    float2* part = (float2*)(smh + XS_H + 3 * W_CH);

    const int tid  = threadIdx.x;
    const int warp = tid >> 5, lane = tid & 31;
    const int wm = warp >> 2;
    const int wn = warp & 3;
    const int g  = lane >> 2;
    const int tq = lane & 3;
    const long blockRow = (long)blockIdx.x * 64;
    uint32_t xs_b = (uint32_t)__cvta_generic_to_shared(XS);
    uint32_t ws_b = (uint32_t)__cvta_generic_to_shared(smh + XS_H);

    // ---- PDL prologue: prime W1 chunks 0,1 (W written >=3 kernels back,
    //      safe before the wait by PDL transitivity), then wait for A.
    {
        const int krow = tid >> 5;
        const int n8 = tid & 31;
        issue_w(W1, 0, 0, ws_b, krow, n8);
        issue_w(W1, 1, 1, ws_b, krow, n8);
    }
    pdl_wait();

    // ---- stage: XS = half( relu(A + bIn) ) ----
    #pragma unroll
    for (int i = 0; i < 8; ++i) {
        int id = i * 256 + tid;
        int row = id >> 5;
        int q = id & 31;
        long r = blockRow + row;
        if (r > M - 1) r = M - 1;
        uint4 v = ((const uint4*)(A + r * 256))[q];
        float4 ba = *(const float4*)(bIn + q * 8);
        float4 bb = *(const float4*)(bIn + q * 8 + 4);
        float f[8];
        float2 t;
        t = __half22float2(*(__half2*)&v.x); f[0] = t.x; f[1] = t.y;
        t = __half22float2(*(__half2*)&v.y); f[2] = t.x; f[3] = t.y;
        t = __half22float2(*(__half2*)&v.z); f[4] = t.x; f[5] = t.y;
        t = __half22float2(*(__half2*)&v.w); f[6] = t.x; f[7] = t.y;
        f[0] = fmaxf(f[0] + ba.x, 0.f); f[1] = fmaxf(f[1] + ba.y, 0.f);
        f[2] = fmaxf(f[2] + ba.z, 0.f); f[3] = fmaxf(f[3] + ba.w, 0.f);
        f[4] = fmaxf(f[4] + bb.x, 0.f); f[5] = fmaxf(f[5] + bb.y, 0.f);
        f[6] = fmaxf(f[6] + bb.z, 0.f); f[7] = fmaxf(f[7] + bb.w, 0.f);
        __half2 h0 = __floats2half2_rn(f[0], f[1]);
        __half2 h1 = __floats2half2_rn(f[2], f[3]);
        __half2 h2 = __floats2half2_rn(f[4], f[5]);
        __half2 h3 = __floats2half2_rn(f[6], f[7]);
        uint4 o;
        o.x = *(uint32_t*)&h0; o.y = *(uint32_t*)&h1;
        o.z = *(uint32_t*)&h2; o.w = *(uint32_t*)&h3;
        *(uint4*)(XS + row * XPH + q * 8) = o;
    }

    float c[2][8][4];
    #pragma unroll
    for (int i = 0; i < 2; ++i)
        #pragma unroll
        for (int j = 0; j < 8; ++j)
            #pragma unroll
            for (int k = 0; k < 4; ++k) c[i][j][k] = 0.f;

    gemm_h(W1, true, xs_b, ws_b, c, tid, wm, wn, lane);

    #pragma unroll
    for (int mt = 0; mt < 2; ++mt)
        #pragma unroll
        for (int nt = 0; nt < 8; ++nt) {
            int col = wn * 64 + nt * 8 + tq * 2;
            float2 bv = *(const float2*)(b1 + col);
            c[mt][nt][0] += bv.x; c[mt][nt][1] += bv.y;
            c[mt][nt][2] += bv.x; c[mt][nt][3] += bv.y;
            if (reluLN) {
                c[mt][nt][0] = fmaxf(c[mt][nt][0], 0.f);
                c[mt][nt][1] = fmaxf(c[mt][nt][1], 0.f);
                c[mt][nt][2] = fmaxf(c[mt][nt][2], 0.f);
                c[mt][nt][3] = fmaxf(c[mt][nt][3], 0.f);
            }
        }

    float s[2][2], ss[2][2];
    #pragma unroll
    for (int mt = 0; mt < 2; ++mt)
        #pragma unroll
        for (int hf = 0; hf < 2; ++hf) {
            float a = 0.f, b = 0.f;
            #pragma unroll
            for (int nt = 0; nt < 8; ++nt) {
                float v0 = c[mt][nt][hf * 2];
                float v1 = c[mt][nt][hf * 2 + 1];
                a += v0 + v1;
                b += v0 * v0 + v1 * v1;
            }
            #pragma unroll
            for (int o = 1; o <= 2; o <<= 1) {
                a += __shfl_xor_sync(0xffffffffu, a, o);
                b += __shfl_xor_sync(0xffffffffu, b, o);
            }
            s[mt][hf] = a;
            ss[mt][hf] = b;
        }
    if (tq == 0) {
        #pragma unroll
        for (int mt = 0; mt < 2; ++mt)
            #pragma unroll
            for (int hf = 0; hf < 2; ++hf) {
                int row = wm * 32 + mt * 16 + hf * 8 + g;
                part[row * 4 + wn] = make_float2(s[mt][hf], ss[mt][hf]);
            }
    }
    __syncthreads();

    #pragma unroll
    for (int mt = 0; mt < 2; ++mt)
        #pragma unroll
        for (int hf = 0; hf < 2; ++hf) {
            int row = wm * 32 + mt * 16 + hf * 8 + g;
            float2 p0 = part[row * 4 + 0];
            float2 p1 = part[row * 4 + 1];
            float2 p2 = part[row * 4 + 2];
            float2 p3 = part[row * 4 + 3];
            float sum = p0.x + p1.x + p2.x + p3.x;
            float sq  = p0.y + p1.y + p2.y + p3.y;
            float mean = sum * (1.f / 256.f);
            float var  = sq * (1.f / 256.f) - mean * mean;
            float rstd = rsqrtf(var + 1e-5f);
            long grow = blockRow + row;
            #pragma unroll
            for (int nt = 0; nt < 8; ++nt) {
                int col = wn * 64 + nt * 8 + tq * 2;
                float2 gv = *(const float2*)(lng + col);
                float2 bv = *(const float2*)(lnb + col);
                float o0 = (c[mt][nt][hf * 2]     - mean) * rstd * gv.x + bv.x;
                float o1 = (c[mt][nt][hf * 2 + 1] - mean) * rstd * gv.y + bv.y;
                if (hasG2) {
                    __half2 h = __floats2half2_rn(o0, o1);
                    *(uint32_t*)(XS + row * XPH + col) = *(uint32_t*)&h;
                } else if (grow < M) {
                    float2 t = {o0, o1};
                    *(float2*)(OutF + grow * 256 + col) = t;
                }
            }
        }
    if (!hasG2) { pdl_launch_dep(); return; }
    __syncthreads();

    #pragma unroll
    for (int i = 0; i < 2; ++i)
        #pragma unroll
        for (int j = 0; j < 8; ++j)
            #pragma unroll
            for (int k = 0; k < 4; ++k) c[i][j][k] = 0.f;

    gemm_h(W2, false, xs_b, ws_b, c, tid, wm, wn, lane);

    #pragma unroll
    for (int mt = 0; mt < 2; ++mt) {
        long rb = blockRow + wm * 32 + mt * 16;
        long r0 = rb + g;
        long r1 = rb + 8 + g;
        #pragma unroll
        for (int nt = 0; nt < 8; ++nt) {
            int col = wn * 64 + nt * 8 + tq * 2;
            if (r0 < M) {
                __half2 h = __floats2half2_rn(c[mt][nt][0], c[mt][nt][1]);
                *(uint32_t*)(OutH + r0 * 256 + col) = *(uint32_t*)&h;
            }
            if (r1 < M) {
                __half2 h = __floats2half2_rn(c[mt][nt][2], c[mt][nt][3]);
                *(uint32_t*)(OutH + r1 * 256 + col) = *(uint32_t*)&h;
            }
        }
    }
    pdl_launch_dep();
}

// --------------------------------- driver ---------------------------------

template <typename K, typename... Args>
static void launch_pdl(K kernel, int grid, int block, size_t smem, Args... args) {
    cudaLaunchConfig_t cfg = {};
    cfg.gridDim = dim3(grid);
    cfg.blockDim = dim3(block);
    cfg.dynamicSmemBytes = smem;
    cfg.stream = 0;
    cudaLaunchAttribute at[1];
    at[0].id = cudaLaunchAttributeProgrammaticStreamSerialization;
    at[0].val.programmaticStreamSerializationAllowed = 1;
    cfg.attrs = at;
    cfg.numAttrs = 1;
    cudaLaunchKernelEx(&cfg, kernel, args...);
}

extern "C" void kernel_launch(void* const* d_in, const int* in_sizes, int n_in,
                              void* d_out, int out_size) {
    const int*   xcat = (const int*)d_in[0];
    const int*   ei   = (const int*)d_in[1];
    const float* e0   = (const float*)d_in[2];
    const float* e1   = (const float*)d_in[3];
    const float* e2   = (const float*)d_in[4];
    const float* e3   = (const float*)d_in[5];
    const float* w1a  = (const float*)d_in[6];
    const float* b1a  = (const float*)d_in[7];
    const float* w1b  = (const float*)d_in[8];
    const float* b1b  = (const float*)d_in[9];
    const float* w2a  = (const float*)d_in[10];
    const float* b2a  = (const float*)d_in[11];
    const float* w2b  = (const float*)d_in[12];
    const float* b2b  = (const float*)d_in[13];
    const float* ln1g = (const float*)d_in[14];
    const float* ln1b = (const float*)d_in[15];
    const float* ln2g = (const float*)d_in[16];
    const float* ln2b = (const float*)d_in[17];

    int M = in_sizes[0] / 4;
    int E = in_sizes[1] / 2;
    int V = in_sizes[2] / 64;

    __half *h0, *h1, *tabh, *hw1b, *hw2a, *hw2b;
    int *deg, *rowptr, *cursor, *csr;
    cudaGetSymbolAddress((void**)&h0, g_h0);
    cudaGetSymbolAddress((void**)&h1, g_h1);
    cudaGetSymbolAddress((void**)&tabh, g_tabh);
    cudaGetSymbolAddress((void**)&hw1b, g_w1b);
    cudaGetSymbolAddress((void**)&hw2a, g_w2a);
    cudaGetSymbolAddress((void**)&hw2b, g_w2b);
    cudaGetSymbolAddress((void**)&deg, g_deg);
    cudaGetSymbolAddress((void**)&rowptr, g_rowptr);
    cudaGetSymbolAddress((void**)&cursor, g_cursor);
    cudaGetSymbolAddress((void**)&csr, g_csr);

    cudaFuncSetAttribute(k_conv, cudaFuncAttributeMaxDynamicSharedMemorySize,
                         CONV_SMEM_BYTES);

    int rowGrid = (M + 7) / 8;
    int convGrid = (M + 63) / 64;

    int nCnt = (E / 4 + 255) / 256;
    int nVb = (V + 7) / 8;
    int nCvt = (3 * DIM * DIM + 2047) / 2048;
    int nFill = nCnt;
    int nZ0 = (M * 32 + 255) / 256;

    cudaMemsetAsync(deg, 0, (size_t)M * sizeof(int), 0);
    launch_pdl(k_front1, nCnt + 4 * nVb + nCvt, 256, 0,
               ei, deg, E, e0, e1, e2, e3, w1a, tabh, V,
               w1b, hw1b, w2a, hw2a, w2b, hw2b, nCnt, nVb);
    launch_pdl(k_scan, 1, 1024, 0, deg, rowptr, cursor, M);
    launch_pdl(k_front2, nFill + nZ0, 256, 0,
               ei, cursor, csr, E, xcat, tabh, h0, M, nFill);

    // conv1: a1 = agg(z0); h = LN1(relu(relu(a1+b1a)@W1b+b1b)); u = h@W2a
    launch_pdl(k_agg, rowGrid, 256, 0, (const __half*)h0, h1, rowptr,
               (const int*)csr, M);
    launch_pdl(k_conv, convGrid, 256, (size_t)CONV_SMEM_BYTES,
               (const __half*)h1, b1a, (const __half*)hw1b, b1b, ln1g, ln1b,
               (const __half*)hw2a, h0, (float*)nullptr, M, 1, 1);

    // conv2: a2 = agg(u); out = LN2(relu(a2+b2a)@W2b+b2b)
    launch_pdl(k_agg, rowGrid, 256, 0, (const __half*)h0, h1, rowptr,
               (const int*)csr, M);
    launch_pdl(k_conv, convGrid, 256, (size_t)CONV_SMEM_BYTES,
               (const __half*)h1, b2a, (const __half*)hw2b, b2b, ln2g, ln2b,
               (const __half*)nullptr, (__half*)nullptr, (float*)d_out,
               M, 0, 0);
}